// round 2
// baseline (speedup 1.0000x reference)
#include <cuda_runtime.h>

#define L_LVL 4
#define B_SZ  128
#define ST_D  512
#define DTOT  1536

// ---------------- scratch (static device arrays; no allocation) ----------------
__device__ float g_Y  [3ull * 4 * 128 * 1536];  // gate GEMM split-K partials (9.4 MB)
__device__ float g_UV [3ull * 4 * 128 * 512];   // u/v GEMM split-K partials (3 MB)
__device__ float g_UVf[4 * 128 * 512];          // final u|v with bias (1 MB)

// ---------------- helpers ----------------
__device__ __forceinline__ unsigned long long pk2(float x, float y) {
    unsigned long long r;
    asm("mov.b64 %0, {%1, %2};" : "=l"(r) : "f"(x), "f"(y));
    return r;
}
__device__ __forceinline__ unsigned long long ffma2(unsigned long long a,
                                                    unsigned long long b,
                                                    unsigned long long c) {
    unsigned long long d;
    asm("fma.rn.f32x2 %0, %1, %2, %3;" : "=l"(d) : "l"(a), "l"(b), "l"(c));
    return d;
}
__device__ __forceinline__ float sigm(float x) { return 1.f / (1.f + __expf(-x)); }

// ---------------- split-K fp32x2 GEMM ----------------
// Y[b, n] += A_split[b, 0:512] . W[n, split*512 : split*512+512]
// A source per split is one contiguous (B,512) array (x / c / h-level slice).
// Grid: (NTOT/64, L, 3). Block: 128 threads. BM=128, BN=64, BK=16.
// Thread tile 8x8 via fma.rn.f32x2 (1 B smem per FMA -> balanced).
#define BM 128
#define BN 64
#define BK 16

__global__ __launch_bounds__(128) void gemm_split(
    const float* __restrict__ A0, const float* __restrict__ A1, const float* __restrict__ A2,
    int lA0, int lA1, int lA2,
    const float* __restrict__ W0, const float* __restrict__ W1, const float* __restrict__ W2,
    int rowsPerMat, int NTOT, int dstUV)
{
    __shared__ float As[BK][BM];
    __shared__ float Bs[BK][BN];

    const int nt = blockIdx.x, l = blockIdx.y, split = blockIdx.z;
    const int tid = threadIdx.x;

    const float* Ab = (split == 0) ? (A0 + (size_t)l * lA0)
                    : (split == 1) ? (A1 + (size_t)l * lA1)
                    :                (A2 + (size_t)l * lA2);
    const float* arow = Ab + tid * ST_D;   // row b = tid (BM == B == 128)

    const int n_local  = tid & 63;
    const int khalf    = tid >> 6;         // 0/1 : which 8-k half this thread loads for B
    const int n_global = nt * BN + n_local;
    const int mat      = n_global / rowsPerMat;
    const int wrowi    = n_global % rowsPerMat;
    const float* Wb    = (mat == 0) ? W0 : ((mat == 1) ? W1 : W2);
    const float* wrow  = Wb + ((size_t)l * rowsPerMat + wrowi) * DTOT + split * 512 + khalf * 8;

    const int tr = tid >> 3;   // 0..15 -> rows tr*8 .. tr*8+7
    const int tc = tid & 7;    // 0..7  -> cols tc*8 .. tc*8+7
    const int r8 = tr * 8, c8 = tc * 8;

    unsigned long long acc[8][4];
#pragma unroll
    for (int i = 0; i < 8; i++)
#pragma unroll
        for (int j = 0; j < 4; j++) acc[i][j] = 0ull;

    for (int k0 = 0; k0 < 512; k0 += BK) {
        float4 av[4];
#pragma unroll
        for (int j = 0; j < 4; j++) av[j] = __ldg((const float4*)(arow + k0 + j * 4));
        float4 bv0 = __ldg((const float4*)(wrow + k0));
        float4 bv1 = __ldg((const float4*)(wrow + k0 + 4));

#pragma unroll
        for (int j = 0; j < 4; j++) {
            As[j * 4 + 0][tid] = av[j].x;
            As[j * 4 + 1][tid] = av[j].y;
            As[j * 4 + 2][tid] = av[j].z;
            As[j * 4 + 3][tid] = av[j].w;
        }
        Bs[khalf * 8 + 0][n_local] = bv0.x;
        Bs[khalf * 8 + 1][n_local] = bv0.y;
        Bs[khalf * 8 + 2][n_local] = bv0.z;
        Bs[khalf * 8 + 3][n_local] = bv0.w;
        Bs[khalf * 8 + 4][n_local] = bv1.x;
        Bs[khalf * 8 + 5][n_local] = bv1.y;
        Bs[khalf * 8 + 6][n_local] = bv1.z;
        Bs[khalf * 8 + 7][n_local] = bv1.w;
        __syncthreads();

#pragma unroll
        for (int k = 0; k < BK; k++) {
            const float4 alo = *(const float4*)&As[k][r8];
            const float4 ahi = *(const float4*)&As[k][r8 + 4];
            const ulonglong2 b01 = *(const ulonglong2*)&Bs[k][c8];
            const ulonglong2 b23 = *(const ulonglong2*)&Bs[k][c8 + 4];
            unsigned long long ad[8];
            ad[0] = pk2(alo.x, alo.x); ad[1] = pk2(alo.y, alo.y);
            ad[2] = pk2(alo.z, alo.z); ad[3] = pk2(alo.w, alo.w);
            ad[4] = pk2(ahi.x, ahi.x); ad[5] = pk2(ahi.y, ahi.y);
            ad[6] = pk2(ahi.z, ahi.z); ad[7] = pk2(ahi.w, ahi.w);
#pragma unroll
            for (int i = 0; i < 8; i++) {
                acc[i][0] = ffma2(ad[i], b01.x, acc[i][0]);
                acc[i][1] = ffma2(ad[i], b01.y, acc[i][1]);
                acc[i][2] = ffma2(ad[i], b23.x, acc[i][2]);
                acc[i][3] = ffma2(ad[i], b23.y, acc[i][3]);
            }
        }
        __syncthreads();
    }

    float* Y = dstUV ? g_UV : g_Y;
#pragma unroll
    for (int i = 0; i < 8; i++) {
        const int rowg = r8 + i;
        unsigned long long* o = (unsigned long long*)
            (Y + (((size_t)split * L_LVL + l) * B_SZ + rowg) * NTOT + nt * BN + c8);
        ((ulonglong2*)o)[0] = make_ulonglong2(acc[i][0], acc[i][1]);
        ((ulonglong2*)o)[1] = make_ulonglong2(acc[i][2], acc[i][3]);
    }
}

// ---------------- gate epilogue: h_new = sig(a)*tanh(p) + sig(b)*h ----------------
__global__ void epi_gates(const float* __restrict__ phi_b, const float* __restrict__ alpha_b,
                          const float* __restrict__ beta_b, const float* __restrict__ h,
                          float* __restrict__ hnew)
{
    int i = blockIdx.x * blockDim.x + threadIdx.x;   // < 4*128*512
    int o  = i & 511;
    int lb = i >> 9;
    int l  = lb >> 7;
    const size_t S = 786432ull;                      // split stride in g_Y
    size_t base = (size_t)lb * DTOT;

    float p  = g_Y[base + o]        + g_Y[S + base + o]        + g_Y[2*S + base + o]        + phi_b  [l*512 + o];
    float a  = g_Y[base + 512 + o]  + g_Y[S + base + 512 + o]  + g_Y[2*S + base + 512 + o]  + alpha_b[l*512 + o];
    float bb = g_Y[base + 1024 + o] + g_Y[S + base + 1024 + o] + g_Y[2*S + base + 1024 + o] + beta_b [l*512 + o];

    hnew[i] = sigm(a) * tanhf(p) + sigm(bb) * h[i];
}

// ---------------- u/v epilogue: sum splits + bias ----------------
__global__ void epi_uv(const float* __restrict__ u_b, const float* __restrict__ v_b)
{
    int i = blockIdx.x * blockDim.x + threadIdx.x;   // < 4*128*512
    int n  = i & 511;
    int lb = i >> 9;
    int l  = lb >> 7;
    const size_t S = 262144ull;                      // split stride in g_UV
    float s = g_UV[i] + g_UV[S + i] + g_UV[2*S + i];
    s += (n < 256) ? u_b[l*256 + n] : v_b[l*256 + (n - 256)];
    g_UVf[i] = s;
}

// ---------------- fused M update: one thread = one (b,r,c4) across all 4 levels ----------------
__device__ __forceinline__ float4 upd(float4 m, float4 ca, float4 cb,
                                      float g, float ee, float u, float4 v)
{
    float4 o;
    o.x = (1.f - g) * m.x + g * 0.5f * (ca.x + cb.x) + ee * u * v.x;
    o.y = (1.f - g) * m.y + g * 0.5f * (ca.y + cb.y) + ee * u * v.y;
    o.z = (1.f - g) * m.z + g * 0.5f * (ca.z + cb.z) + ee * u * v.z;
    o.w = (1.f - g) * m.w + g * 0.5f * (ca.w + cb.w) + ee * u * v.w;
    return o;
}

__global__ void mem_update(const float* __restrict__ M,
                           const float* __restrict__ gamma_logits,
                           const float* __restrict__ eta_logits,
                           float* __restrict__ outM)
{
    size_t idx = (size_t)blockIdx.x * blockDim.x + threadIdx.x;   // < 2097152
    size_t e = idx * 4;                                           // element within (B,R,C)
    int b  = (int)(e >> 16);        // R*C = 65536
    int rc = (int)(e & 65535);
    int r  = rc >> 8;
    int c  = rc & 255;
    const size_t LVL = 8388608ull;  // B*R*C

    float4 m0 = __ldg((const float4*)(M + e));
    float4 m1 = __ldg((const float4*)(M + LVL + e));
    float4 m2 = __ldg((const float4*)(M + 2*LVL + e));
    float4 m3 = __ldg((const float4*)(M + 3*LVL + e));

    float g0 = sigm(gamma_logits[0]), g1 = sigm(gamma_logits[1]);
    float g2 = sigm(gamma_logits[2]), g3 = sigm(gamma_logits[3]);
    float e0 = sigm(eta_logits[0]),   e1 = sigm(eta_logits[1]);
    float e2 = sigm(eta_logits[2]),   e3 = sigm(eta_logits[3]);

    float u0 = g_UVf[(0*128 + b)*512 + r];
    float u1 = g_UVf[(1*128 + b)*512 + r];
    float u2 = g_UVf[(2*128 + b)*512 + r];
    float u3 = g_UVf[(3*128 + b)*512 + r];
    float4 v0 = *(const float4*)&g_UVf[(0*128 + b)*512 + 256 + c];
    float4 v1 = *(const float4*)&g_UVf[(1*128 + b)*512 + 256 + c];
    float4 v2 = *(const float4*)&g_UVf[(2*128 + b)*512 + 256 + c];
    float4 v3 = *(const float4*)&g_UVf[(3*128 + b)*512 + 256 + c];

    // comm: l=0 -> (m0,m1); l=1 -> (m0,m2); l=2 -> (m1,m3); l=3 -> (m2,m3)
    *(float4*)(outM + e)           = upd(m0, m0, m1, g0, e0, u0, v0);
    *(float4*)(outM + LVL + e)     = upd(m1, m0, m2, g1, e1, u1, v1);
    *(float4*)(outM + 2*LVL + e)   = upd(m2, m1, m3, g2, e2, u2, v2);
    *(float4*)(outM + 3*LVL + e)   = upd(m3, m2, m3, g3, e3, u3, v3);
}

// ---------------- launch ----------------
extern "C" void kernel_launch(void* const* d_in, const int* in_sizes, int n_in,
                              void* d_out, int out_size)
{
    const float* x       = (const float*)d_in[0];
    const float* c       = (const float*)d_in[1];
    const float* h       = (const float*)d_in[2];
    const float* M       = (const float*)d_in[3];
    const float* phi_w   = (const float*)d_in[4];
    const float* phi_b   = (const float*)d_in[5];
    const float* alpha_w = (const float*)d_in[6];
    const float* alpha_b = (const float*)d_in[7];
    const float* beta_w  = (const float*)d_in[8];
    const float* beta_b  = (const float*)d_in[9];
    const float* u_w     = (const float*)d_in[10];
    const float* u_b     = (const float*)d_in[11];
    const float* v_w     = (const float*)d_in[12];
    const float* v_b     = (const float*)d_in[13];
    const float* gam     = (const float*)d_in[14];
    const float* eta     = (const float*)d_in[15];

    float* hnew = (float*)d_out;                 // (L,B,ST)  = 262144 floats
    float* outM = hnew + 4 * 128 * 512;          // (L,B,R,C) = 33554432 floats

    // 1) gate GEMM: gi = [x | c | h_l], N = phi|alpha|beta (1536)
    gemm_split<<<dim3(24, 4, 3), 128>>>(x, c, h, 0, 0, 65536,
                                        phi_w, alpha_w, beta_w, 512, 1536, 0);
    // 2) h_new epilogue (writes into d_out, also consumed by the next GEMM)
    epi_gates<<<1024, 256>>>(phi_b, alpha_b, beta_b, h, hnew);
    // 3) u/v GEMM: wv = [h_new | x | c], N = u|v (512)
    gemm_split<<<dim3(8, 4, 3), 128>>>(hnew, x, c, 65536, 0, 0,
                                       u_w, v_w, v_w, 256, 512, 1);
    // 4) u/v bias epilogue
    epi_uv<<<1024, 256>>>(u_b, v_b);
    // 5) fused memory update (reads each M element once, writes each M_new once)
    mem_update<<<8192, 256>>>(M, gam, eta, outM);
}

// round 3
// speedup vs baseline: 1.4058x; 1.4058x over previous
#include <cuda_runtime.h>
#include <cstdint>

#define L_LVL 4
#define B_SZ  128

// ---------------- scratch (static device arrays; no allocation) ----------------
__device__ float g_Y  [3ull * 4 * 128 * 1536];  // gate GEMM split-K partials
__device__ float g_UV [3ull * 4 * 128 * 512];   // u/v GEMM split-K partials
__device__ float g_UVf[4 * 128 * 512];          // final u|v with bias

__device__ __forceinline__ float sigm(float x) { return 1.f / (1.f + __expf(-x)); }
__device__ __forceinline__ uint32_t f2tf32(float x) {
    uint32_t r; asm("cvt.rna.tf32.f32 %0, %1;" : "=r"(r) : "f"(x)); return r;
}

// ---------------- split-K tf32 tensor-core GEMM ----------------
// Y[(split,l,b), n] = A_split[b, 0:512] . W[n, split*512 : +512]
// BM=128 (batch), BN=128, BK=32. 256 threads = 8 warps in 2(m) x 4(n).
// Each warp: 64x32 tile = 4x4 grid of m16n8k8 tf32 mma.
#define BK  32
#define PAD 8
#define SROW 136   // 128 + PAD; 136 % 32 == 8 -> conflict-free frag gathers

__global__ __launch_bounds__(256) void gemm_tf32(
    const float* __restrict__ A0, const float* __restrict__ A1, const float* __restrict__ A2,
    int lA0, int lA1, int lA2,
    const float* __restrict__ W0, const float* __restrict__ W1, const float* __restrict__ W2,
    int rowsPerMat, int NTOT, int dstUV)
{
    __shared__ uint32_t As[BK][SROW];   // [k][m], tf32 bits
    __shared__ uint32_t Bs[BK][SROW];   // [k][n], tf32 bits

    const int nt = blockIdx.x, l = blockIdx.y, split = blockIdx.z;
    const int tid = threadIdx.x;
    const int lane = tid & 31, warp = tid >> 5;
    const int m0w = (warp & 1) * 64;    // warp m-origin
    const int n0w = (warp >> 1) * 32;   // warp n-origin

    const float* Ab = (split == 0) ? (A0 + (size_t)l * lA0)
                    : (split == 1) ? (A1 + (size_t)l * lA1)
                    :                (A2 + (size_t)l * lA2);

    // tile loaders: 256 threads; lm = row (m or n), kg selects 16-k half
    const int lm = tid & 127;
    const int kg = tid >> 7;
    const float* arow = Ab + lm * 512 + kg * 16;

    const int n_global = nt * 128 + lm;
    const int mat      = n_global / rowsPerMat;
    const int wrowi    = n_global % rowsPerMat;
    const float* Wb    = (mat == 0) ? W0 : ((mat == 1) ? W1 : W2);
    const float* wrow  = Wb + ((size_t)l * rowsPerMat + wrowi) * 1536 + split * 512 + kg * 16;

    float acc[4][4][4];
#pragma unroll
    for (int i = 0; i < 4; i++)
#pragma unroll
        for (int j = 0; j < 4; j++)
#pragma unroll
            for (int f = 0; f < 4; f++) acc[i][j][f] = 0.f;

    const int fc  = lane & 3;    // frag col group (k within 4)
    const int frw = lane >> 2;   // frag row (0..7)

    for (int k0 = 0; k0 < 512; k0 += BK) {
#pragma unroll
        for (int j = 0; j < 4; j++) {
            float4 v = __ldg((const float4*)(arow + k0 + j * 4));
            int k = kg * 16 + j * 4;
            As[k + 0][lm] = f2tf32(v.x); As[k + 1][lm] = f2tf32(v.y);
            As[k + 2][lm] = f2tf32(v.z); As[k + 3][lm] = f2tf32(v.w);
        }
#pragma unroll
        for (int j = 0; j < 4; j++) {
            float4 v = __ldg((const float4*)(wrow + k0 + j * 4));
            int k = kg * 16 + j * 4;
            Bs[k + 0][lm] = f2tf32(v.x); Bs[k + 1][lm] = f2tf32(v.y);
            Bs[k + 2][lm] = f2tf32(v.z); Bs[k + 3][lm] = f2tf32(v.w);
        }
        __syncthreads();

#pragma unroll
        for (int kk = 0; kk < BK; kk += 8) {
            uint32_t a[4][4], b[4][2];
#pragma unroll
            for (int mt = 0; mt < 4; mt++) {
                int m = m0w + mt * 16 + frw;
                a[mt][0] = As[kk + fc][m];
                a[mt][1] = As[kk + fc][m + 8];
                a[mt][2] = As[kk + fc + 4][m];
                a[mt][3] = As[kk + fc + 4][m + 8];
            }
#pragma unroll
            for (int ntt = 0; ntt < 4; ntt++) {
                int n = n0w + ntt * 8 + frw;
                b[ntt][0] = Bs[kk + fc][n];
                b[ntt][1] = Bs[kk + fc + 4][n];
            }
#pragma unroll
            for (int mt = 0; mt < 4; mt++)
#pragma unroll
                for (int ntt = 0; ntt < 4; ntt++) {
                    asm volatile(
                        "mma.sync.aligned.m16n8k8.row.col.f32.tf32.tf32.f32 "
                        "{%0,%1,%2,%3}, {%4,%5,%6,%7}, {%8,%9}, {%0,%1,%2,%3};"
                        : "+f"(acc[mt][ntt][0]), "+f"(acc[mt][ntt][1]),
                          "+f"(acc[mt][ntt][2]), "+f"(acc[mt][ntt][3])
                        : "r"(a[mt][0]), "r"(a[mt][1]), "r"(a[mt][2]), "r"(a[mt][3]),
                          "r"(b[ntt][0]), "r"(b[ntt][1]));
                }
        }
        __syncthreads();
    }

    float* Y = dstUV ? g_UV : g_Y;
    const int colq = (lane & 3) * 2;
#pragma unroll
    for (int mt = 0; mt < 4; mt++) {
        int m = m0w + mt * 16 + frw;
        size_t base  = (((size_t)split * L_LVL + l) * B_SZ + m) * NTOT + nt * 128 + n0w;
        size_t base2 = base + 8ull * NTOT;
#pragma unroll
        for (int ntt = 0; ntt < 4; ntt++) {
            *(float2*)&Y[base  + ntt * 8 + colq] = make_float2(acc[mt][ntt][0], acc[mt][ntt][1]);
            *(float2*)&Y[base2 + ntt * 8 + colq] = make_float2(acc[mt][ntt][2], acc[mt][ntt][3]);
        }
    }
}

// ---------------- gate epilogue: h_new = sig(a)*tanh(p) + sig(b)*h ----------------
__global__ void epi_gates(const float* __restrict__ phi_b, const float* __restrict__ alpha_b,
                          const float* __restrict__ beta_b, const float* __restrict__ h,
                          float* __restrict__ hnew)
{
    int i = blockIdx.x * blockDim.x + threadIdx.x;   // < 4*128*512
    int o  = i & 511;
    int lb = i >> 9;
    int l  = lb >> 7;
    const size_t S = 786432ull;                      // split stride in g_Y
    size_t base = (size_t)lb * 1536;

    float p  = g_Y[base + o]        + g_Y[S + base + o]        + g_Y[2*S + base + o]        + phi_b  [l*512 + o];
    float a  = g_Y[base + 512 + o]  + g_Y[S + base + 512 + o]  + g_Y[2*S + base + 512 + o]  + alpha_b[l*512 + o];
    float bb = g_Y[base + 1024 + o] + g_Y[S + base + 1024 + o] + g_Y[2*S + base + 1024 + o] + beta_b [l*512 + o];

    hnew[i] = sigm(a) * tanhf(p) + sigm(bb) * h[i];
}

// ---------------- u/v epilogue: sum splits + bias ----------------
__global__ void epi_uv(const float* __restrict__ u_b, const float* __restrict__ v_b)
{
    int i = blockIdx.x * blockDim.x + threadIdx.x;   // < 4*128*512
    int n  = i & 511;
    int lb = i >> 9;
    int l  = lb >> 7;
    const size_t S = 262144ull;                      // split stride in g_UV
    float s = g_UV[i] + g_UV[S + i] + g_UV[2*S + i];
    s += (n < 256) ? u_b[l*256 + n] : v_b[l*256 + (n - 256)];
    g_UVf[i] = s;
}

// ---------------- fused M update ----------------
__device__ __forceinline__ float4 upd(float4 m, float4 ca, float4 cb,
                                      float g, float ee, float u, float4 v)
{
    float4 o;
    o.x = (1.f - g) * m.x + g * 0.5f * (ca.x + cb.x) + ee * u * v.x;
    o.y = (1.f - g) * m.y + g * 0.5f * (ca.y + cb.y) + ee * u * v.y;
    o.z = (1.f - g) * m.z + g * 0.5f * (ca.z + cb.z) + ee * u * v.z;
    o.w = (1.f - g) * m.w + g * 0.5f * (ca.w + cb.w) + ee * u * v.w;
    return o;
}

__global__ void mem_update(const float* __restrict__ M,
                           const float* __restrict__ gamma_logits,
                           const float* __restrict__ eta_logits,
                           float* __restrict__ outM)
{
    size_t idx = (size_t)blockIdx.x * blockDim.x + threadIdx.x;   // < 2097152
    size_t e = idx * 4;
    int b  = (int)(e >> 16);
    int rc = (int)(e & 65535);
    int r  = rc >> 8;
    int c  = rc & 255;
    const size_t LVL = 8388608ull;  // B*R*C

    float4 m0 = __ldg((const float4*)(M + e));
    float4 m1 = __ldg((const float4*)(M + LVL + e));
    float4 m2 = __ldg((const float4*)(M + 2*LVL + e));
    float4 m3 = __ldg((const float4*)(M + 3*LVL + e));

    float g0 = sigm(gamma_logits[0]), g1 = sigm(gamma_logits[1]);
    float g2 = sigm(gamma_logits[2]), g3 = sigm(gamma_logits[3]);
    float e0 = sigm(eta_logits[0]),   e1 = sigm(eta_logits[1]);
    float e2 = sigm(eta_logits[2]),   e3 = sigm(eta_logits[3]);

    float u0 = g_UVf[(0*128 + b)*512 + r];
    float u1 = g_UVf[(1*128 + b)*512 + r];
    float u2 = g_UVf[(2*128 + b)*512 + r];
    float u3 = g_UVf[(3*128 + b)*512 + r];
    float4 v0 = *(const float4*)&g_UVf[(0*128 + b)*512 + 256 + c];
    float4 v1 = *(const float4*)&g_UVf[(1*128 + b)*512 + 256 + c];
    float4 v2 = *(const float4*)&g_UVf[(2*128 + b)*512 + 256 + c];
    float4 v3 = *(const float4*)&g_UVf[(3*128 + b)*512 + 256 + c];

    // comm: l=0 -> (m0,m1); l=1 -> (m0,m2); l=2 -> (m1,m3); l=3 -> (m2,m3)
    *(float4*)(outM + e)           = upd(m0, m0, m1, g0, e0, u0, v0);
    *(float4*)(outM + LVL + e)     = upd(m1, m0, m2, g1, e1, u1, v1);
    *(float4*)(outM + 2*LVL + e)   = upd(m2, m1, m3, g2, e2, u2, v2);
    *(float4*)(outM + 3*LVL + e)   = upd(m3, m2, m3, g3, e3, u3, v3);
}

// ---------------- launch ----------------
extern "C" void kernel_launch(void* const* d_in, const int* in_sizes, int n_in,
                              void* d_out, int out_size)
{
    const float* x       = (const float*)d_in[0];
    const float* c       = (const float*)d_in[1];
    const float* h       = (const float*)d_in[2];
    const float* M       = (const float*)d_in[3];
    const float* phi_w   = (const float*)d_in[4];
    const float* phi_b   = (const float*)d_in[5];
    const float* alpha_w = (const float*)d_in[6];
    const float* alpha_b = (const float*)d_in[7];
    const float* beta_w  = (const float*)d_in[8];
    const float* beta_b  = (const float*)d_in[9];
    const float* u_w     = (const float*)d_in[10];
    const float* u_b     = (const float*)d_in[11];
    const float* v_w     = (const float*)d_in[12];
    const float* v_b     = (const float*)d_in[13];
    const float* gam     = (const float*)d_in[14];
    const float* eta     = (const float*)d_in[15];

    float* hnew = (float*)d_out;                 // (L,B,ST)
    float* outM = hnew + 4 * 128 * 512;          // (L,B,R,C)

    // 1) gate GEMM: gi = [x | c | h_l], N = phi|alpha|beta (1536)
    gemm_tf32<<<dim3(12, 4, 3), 256>>>(x, c, h, 0, 0, 65536,
                                       phi_w, alpha_w, beta_w, 512, 1536, 0);
    // 2) h_new epilogue
    epi_gates<<<1024, 256>>>(phi_b, alpha_b, beta_b, h, hnew);
    // 3) u/v GEMM: wv = [h_new | x | c], N = u|v (512)
    gemm_tf32<<<dim3(4, 4, 3), 256>>>(hnew, x, c, 65536, 0, 0,
                                      u_w, v_w, v_w, 256, 512, 1);
    // 4) u/v bias epilogue
    epi_uv<<<1024, 256>>>(u_b, v_b);
    // 5) fused memory update
    mem_update<<<8192, 256>>>(M, gam, eta, outM);
}

// round 4
// speedup vs baseline: 1.6181x; 1.1510x over previous
#include <cuda_runtime.h>
#include <cstdint>

#define L_LVL 4
#define B_SZ  128

// ---------------- scratch (static device arrays; no allocation) ----------------
__device__ float g_Y  [3ull * 4 * 128 * 1536];  // gate GEMM split-K partials (3 splits)
__device__ float g_UV [6ull * 4 * 128 * 512];   // u/v GEMM split-K partials (6 splits)
__device__ float g_UVf[4 * 128 * 512];          // final u|v with bias

__device__ __forceinline__ float sigm(float x) { return 1.f / (1.f + __expf(-x)); }
__device__ __forceinline__ uint32_t f2tf32(float x) {
    uint32_t r; asm("cvt.rna.tf32.f32 %0, %1;" : "=r"(r) : "f"(x)); return r;
}

// ---------------- split-K tf32 tensor-core GEMM, double-buffered ----------------
// Y[(split,l,b), n] = A_seg[b, kOff:kOff+kLen] . W[n, seg*512+kOff : +kLen]
// BM=128 (batch), BN=128, BK=16. 256 threads = 8 warps in 2(m) x 4(n).
// Each warp: 64x32 = 4x4 grid of m16n8k8 tf32 mma. 2-stage smem pipeline.
#define BK   16
#define SROW 136   // 128 + 8; (8k+m)%32 covers all banks -> conflict-free frags

__global__ __launch_bounds__(256) void gemm_tf32(
    const float* __restrict__ A0, const float* __restrict__ A1, const float* __restrict__ A2,
    int lA0, int lA1, int lA2,
    const float* __restrict__ W0, const float* __restrict__ W1, const float* __restrict__ W2,
    int rowsPerMat, int NTOT, int khbits, int dstUV)
{
    __shared__ uint32_t As[2][BK][SROW];
    __shared__ uint32_t Bs[2][BK][SROW];

    const int nt = blockIdx.x, l = blockIdx.y, split = blockIdx.z;
    const int tid = threadIdx.x;
    const int lane = tid & 31, warp = tid >> 5;
    const int m0w = (warp & 1) * 64;
    const int n0w = (warp >> 1) * 32;

    const int seg  = split >> khbits;
    const int kh   = split & ((1 << khbits) - 1);
    const int kLen = 512 >> khbits;
    const int kOff = kh * kLen;
    const int NIT  = kLen / BK;

    const float* Ab = (seg == 0) ? (A0 + (size_t)l * lA0)
                    : (seg == 1) ? (A1 + (size_t)l * lA1)
                    :              (A2 + (size_t)l * lA2);

    // tile loaders: lm = row (m or n), kg selects 8-k half of the 16-k tile
    const int lm = tid & 127;
    const int kg = tid >> 7;
    const float* arow = Ab + lm * 512 + kOff + kg * 8;

    const int n_global = nt * 128 + lm;
    const int mat      = n_global / rowsPerMat;
    const int wrowi    = n_global % rowsPerMat;
    const float* Wb    = (mat == 0) ? W0 : ((mat == 1) ? W1 : W2);
    const float* wrow  = Wb + ((size_t)l * rowsPerMat + wrowi) * 1536 + seg * 512 + kOff + kg * 8;

    float acc[4][4][4];
#pragma unroll
    for (int i = 0; i < 4; i++)
#pragma unroll
        for (int j = 0; j < 4; j++)
#pragma unroll
            for (int f = 0; f < 4; f++) acc[i][j][f] = 0.f;

    const int fc  = lane & 3;
    const int frw = lane >> 2;
    const int kb  = kg * 8;

    // ---- prologue: tile 0 ----
    float4 ra0 = __ldg((const float4*)(arow));
    float4 ra1 = __ldg((const float4*)(arow + 4));
    float4 rb0 = __ldg((const float4*)(wrow));
    float4 rb1 = __ldg((const float4*)(wrow + 4));
#pragma unroll
    for (int i = 0; i < 1; i++) {  // store tile 0 into buf 0
        As[0][kb + 0][lm] = f2tf32(ra0.x); As[0][kb + 1][lm] = f2tf32(ra0.y);
        As[0][kb + 2][lm] = f2tf32(ra0.z); As[0][kb + 3][lm] = f2tf32(ra0.w);
        As[0][kb + 4][lm] = f2tf32(ra1.x); As[0][kb + 5][lm] = f2tf32(ra1.y);
        As[0][kb + 6][lm] = f2tf32(ra1.z); As[0][kb + 7][lm] = f2tf32(ra1.w);
        Bs[0][kb + 0][lm] = f2tf32(rb0.x); Bs[0][kb + 1][lm] = f2tf32(rb0.y);
        Bs[0][kb + 2][lm] = f2tf32(rb0.z); Bs[0][kb + 3][lm] = f2tf32(rb0.w);
        Bs[0][kb + 4][lm] = f2tf32(rb1.x); Bs[0][kb + 5][lm] = f2tf32(rb1.y);
        Bs[0][kb + 6][lm] = f2tf32(rb1.z); Bs[0][kb + 7][lm] = f2tf32(rb1.w);
    }
    __syncthreads();

    for (int it = 0; it < NIT; it++) {
        const int nxt = it + 1;
        if (nxt < NIT) {   // prefetch next tile into registers (latency hidden by compute)
            ra0 = __ldg((const float4*)(arow + nxt * BK));
            ra1 = __ldg((const float4*)(arow + nxt * BK + 4));
            rb0 = __ldg((const float4*)(wrow + nxt * BK));
            rb1 = __ldg((const float4*)(wrow + nxt * BK + 4));
        }

        const int buf = it & 1;
#pragma unroll
        for (int kk = 0; kk < BK; kk += 8) {
            uint32_t a[4][4], b[4][2];
#pragma unroll
            for (int mt = 0; mt < 4; mt++) {
                int m = m0w + mt * 16 + frw;
                a[mt][0] = As[buf][kk + fc][m];
                a[mt][1] = As[buf][kk + fc][m + 8];
                a[mt][2] = As[buf][kk + fc + 4][m];
                a[mt][3] = As[buf][kk + fc + 4][m + 8];
            }
#pragma unroll
            for (int ntt = 0; ntt < 4; ntt++) {
                int n = n0w + ntt * 8 + frw;
                b[ntt][0] = Bs[buf][kk + fc][n];
                b[ntt][1] = Bs[buf][kk + fc + 4][n];
            }
#pragma unroll
            for (int mt = 0; mt < 4; mt++)
#pragma unroll
                for (int ntt = 0; ntt < 4; ntt++) {
                    asm volatile(
                        "mma.sync.aligned.m16n8k8.row.col.f32.tf32.tf32.f32 "
                        "{%0,%1,%2,%3}, {%4,%5,%6,%7}, {%8,%9}, {%0,%1,%2,%3};"
                        : "+f"(acc[mt][ntt][0]), "+f"(acc[mt][ntt][1]),
                          "+f"(acc[mt][ntt][2]), "+f"(acc[mt][ntt][3])
                        : "r"(a[mt][0]), "r"(a[mt][1]), "r"(a[mt][2]), "r"(a[mt][3]),
                          "r"(b[ntt][0]), "r"(b[ntt][1]));
                }
        }
        __syncthreads();

        if (nxt < NIT) {
            const int nb = nxt & 1;
            As[nb][kb + 0][lm] = f2tf32(ra0.x); As[nb][kb + 1][lm] = f2tf32(ra0.y);
            As[nb][kb + 2][lm] = f2tf32(ra0.z); As[nb][kb + 3][lm] = f2tf32(ra0.w);
            As[nb][kb + 4][lm] = f2tf32(ra1.x); As[nb][kb + 5][lm] = f2tf32(ra1.y);
            As[nb][kb + 6][lm] = f2tf32(ra1.z); As[nb][kb + 7][lm] = f2tf32(ra1.w);
            Bs[nb][kb + 0][lm] = f2tf32(rb0.x); Bs[nb][kb + 1][lm] = f2tf32(rb0.y);
            Bs[nb][kb + 2][lm] = f2tf32(rb0.z); Bs[nb][kb + 3][lm] = f2tf32(rb0.w);
            Bs[nb][kb + 4][lm] = f2tf32(rb1.x); Bs[nb][kb + 5][lm] = f2tf32(rb1.y);
            Bs[nb][kb + 6][lm] = f2tf32(rb1.z); Bs[nb][kb + 7][lm] = f2tf32(rb1.w);
            __syncthreads();
        }
    }

    float* Y = dstUV ? g_UV : g_Y;
    const int colq = (lane & 3) * 2;
#pragma unroll
    for (int mt = 0; mt < 4; mt++) {
        int m = m0w + mt * 16 + frw;
        size_t base  = (((size_t)split * L_LVL + l) * B_SZ + m) * NTOT + nt * 128 + n0w;
        size_t base2 = base + 8ull * NTOT;
#pragma unroll
        for (int ntt = 0; ntt < 4; ntt++) {
            *(float2*)&Y[base  + ntt * 8 + colq] = make_float2(acc[mt][ntt][0], acc[mt][ntt][1]);
            *(float2*)&Y[base2 + ntt * 8 + colq] = make_float2(acc[mt][ntt][2], acc[mt][ntt][3]);
        }
    }
}

// ---------------- gate epilogue: h_new = sig(a)*tanh(p) + sig(b)*h ----------------
__global__ void epi_gates(const float* __restrict__ phi_b, const float* __restrict__ alpha_b,
                          const float* __restrict__ beta_b, const float* __restrict__ h,
                          float* __restrict__ hnew)
{
    int i = blockIdx.x * blockDim.x + threadIdx.x;   // < 4*128*512
    int o  = i & 511;
    int lb = i >> 9;
    int l  = lb >> 7;
    const size_t S = 786432ull;                      // split stride in g_Y
    size_t base = (size_t)lb * 1536;

    float p  = g_Y[base + o]        + g_Y[S + base + o]        + g_Y[2*S + base + o]        + phi_b  [l*512 + o];
    float a  = g_Y[base + 512 + o]  + g_Y[S + base + 512 + o]  + g_Y[2*S + base + 512 + o]  + alpha_b[l*512 + o];
    float bb = g_Y[base + 1024 + o] + g_Y[S + base + 1024 + o] + g_Y[2*S + base + 1024 + o] + beta_b [l*512 + o];

    hnew[i] = sigm(a) * tanhf(p) + sigm(bb) * h[i];
}

// ---------------- u/v epilogue: sum 6 splits + bias ----------------
__global__ void epi_uv(const float* __restrict__ u_b, const float* __restrict__ v_b)
{
    int i = blockIdx.x * blockDim.x + threadIdx.x;   // < 4*128*512
    int n  = i & 511;
    int lb = i >> 9;
    int l  = lb >> 7;
    const size_t S = 262144ull;                      // split stride in g_UV
    float s = 0.f;
#pragma unroll
    for (int sp = 0; sp < 6; sp++) s += g_UV[sp * S + i];
    s += (n < 256) ? u_b[l*256 + n] : v_b[l*256 + (n - 256)];
    g_UVf[i] = s;
}

// ---------------- fused M update ----------------
__device__ __forceinline__ float4 upd(float4 m, float4 ca, float4 cb,
                                      float g, float ee, float u, float4 v)
{
    float4 o;
    o.x = (1.f - g) * m.x + g * 0.5f * (ca.x + cb.x) + ee * u * v.x;
    o.y = (1.f - g) * m.y + g * 0.5f * (ca.y + cb.y) + ee * u * v.y;
    o.z = (1.f - g) * m.z + g * 0.5f * (ca.z + cb.z) + ee * u * v.z;
    o.w = (1.f - g) * m.w + g * 0.5f * (ca.w + cb.w) + ee * u * v.w;
    return o;
}

__global__ void mem_update(const float* __restrict__ M,
                           const float* __restrict__ gamma_logits,
                           const float* __restrict__ eta_logits,
                           float* __restrict__ outM)
{
    size_t idx = (size_t)blockIdx.x * blockDim.x + threadIdx.x;   // < 2097152
    size_t e = idx * 4;
    int b  = (int)(e >> 16);
    int rc = (int)(e & 65535);
    int r  = rc >> 8;
    int c  = rc & 255;
    const size_t LVL = 8388608ull;  // B*R*C

    float4 m0 = __ldg((const float4*)(M + e));
    float4 m1 = __ldg((const float4*)(M + LVL + e));
    float4 m2 = __ldg((const float4*)(M + 2*LVL + e));
    float4 m3 = __ldg((const float4*)(M + 3*LVL + e));

    float g0 = sigm(gamma_logits[0]), g1 = sigm(gamma_logits[1]);
    float g2 = sigm(gamma_logits[2]), g3 = sigm(gamma_logits[3]);
    float e0 = sigm(eta_logits[0]),   e1 = sigm(eta_logits[1]);
    float e2 = sigm(eta_logits[2]),   e3 = sigm(eta_logits[3]);

    float u0 = g_UVf[(0*128 + b)*512 + r];
    float u1 = g_UVf[(1*128 + b)*512 + r];
    float u2 = g_UVf[(2*128 + b)*512 + r];
    float u3 = g_UVf[(3*128 + b)*512 + r];
    float4 v0 = *(const float4*)&g_UVf[(0*128 + b)*512 + 256 + c];
    float4 v1 = *(const float4*)&g_UVf[(1*128 + b)*512 + 256 + c];
    float4 v2 = *(const float4*)&g_UVf[(2*128 + b)*512 + 256 + c];
    float4 v3 = *(const float4*)&g_UVf[(3*128 + b)*512 + 256 + c];

    // comm: l=0 -> (m0,m1); l=1 -> (m0,m2); l=2 -> (m1,m3); l=3 -> (m2,m3)
    *(float4*)(outM + e)           = upd(m0, m0, m1, g0, e0, u0, v0);
    *(float4*)(outM + LVL + e)     = upd(m1, m0, m2, g1, e1, u1, v1);
    *(float4*)(outM + 2*LVL + e)   = upd(m2, m1, m3, g2, e2, u2, v2);
    *(float4*)(outM + 3*LVL + e)   = upd(m3, m2, m3, g3, e3, u3, v3);
}

// ---------------- launch ----------------
extern "C" void kernel_launch(void* const* d_in, const int* in_sizes, int n_in,
                              void* d_out, int out_size)
{
    const float* x       = (const float*)d_in[0];
    const float* c       = (const float*)d_in[1];
    const float* h       = (const float*)d_in[2];
    const float* M       = (const float*)d_in[3];
    const float* phi_w   = (const float*)d_in[4];
    const float* phi_b   = (const float*)d_in[5];
    const float* alpha_w = (const float*)d_in[6];
    const float* alpha_b = (const float*)d_in[7];
    const float* beta_w  = (const float*)d_in[8];
    const float* beta_b  = (const float*)d_in[9];
    const float* u_w     = (const float*)d_in[10];
    const float* u_b     = (const float*)d_in[11];
    const float* v_w     = (const float*)d_in[12];
    const float* v_b     = (const float*)d_in[13];
    const float* gam     = (const float*)d_in[14];
    const float* eta     = (const float*)d_in[15];

    float* hnew = (float*)d_out;                 // (L,B,ST)
    float* outM = hnew + 4 * 128 * 512;          // (L,B,R,C)

    // 1) gate GEMM: gi = [x | c | h_l], N = phi|alpha|beta (1536), 3 K-splits
    gemm_tf32<<<dim3(12, 4, 3), 256>>>(x, c, h, 0, 0, 65536,
                                       phi_w, alpha_w, beta_w, 512, 1536, 0, 0);
    // 2) h_new epilogue
    epi_gates<<<1024, 256>>>(phi_b, alpha_b, beta_b, h, hnew);
    // 3) u/v GEMM: wv = [h_new | x | c], N = u|v (512), 6 K-splits
    gemm_tf32<<<dim3(4, 4, 6), 256>>>(hnew, x, c, 65536, 0, 0,
                                      u_w, v_w, v_w, 256, 512, 1, 1);
    // 4) u/v bias epilogue
    epi_uv<<<1024, 256>>>(u_b, v_b);
    // 5) fused memory update
    mem_update<<<8192, 256>>>(M, gam, eta, outM);
}